// round 16
// baseline (speedup 1.0000x reference)
#include <cuda_runtime.h>
#include <math_constants.h>

#define BS   16
#define NQ   1024
#define NTGT 96
#define NCLS 4
#define DD   6
#define TOT_T (BS*NTGT)   // 1536
#define MM   NQ           // columns (queries) = 1024
#define NN   NTGT         // rows (targets)    = 96
#define NWARP 4
#define TPB  (NWARP*32)   // 128

// transposed diagonal cost blocks: costT[b][i][q], i=target, q=query
__device__ float g_costT[BS * NTGT * NQ];   // ~6.3 MB static device scratch

// ---------------------------------------------------------------------------
// Kernel 1: build C = L1cdist(pred_boxes, tgt_boxes) - softmax(pred_logits)[tgt_ids]
// Also writes the per-batch diagonal block, transposed, into g_costT.
// ---------------------------------------------------------------------------
__global__ __launch_bounds__(256)
void build_cost_kernel(const float* __restrict__ logits,
                       const float* __restrict__ boxes,
                       const int*   __restrict__ labels,
                       const float* __restrict__ tgt,
                       float* __restrict__ C, int writeC)
{
    __shared__ float s_tb[TOT_T * DD];   // 36 KB
    __shared__ int   s_lab[TOT_T];       // 6 KB
    const int tid = threadIdx.x;
    for (int idx = tid; idx < TOT_T * DD; idx += 256) s_tb[idx] = tgt[idx];
    for (int idx = tid; idx < TOT_T;      idx += 256) s_lab[idx] = labels[idx];
    __syncthreads();

    const int ROWS = 16;
    const int r0 = blockIdx.x * ROWS;
    for (int rr = 0; rr < ROWS; rr++) {
        const int r = r0 + rr;
        const int b = r >> 10;
        const int q = r & 1023;

        float l0 = logits[r*4+0], l1 = logits[r*4+1];
        float l2 = logits[r*4+2], l3 = logits[r*4+3];
        float mx = fmaxf(fmaxf(l0,l1), fmaxf(l2,l3));
        float e0 = expf(l0-mx), e1 = expf(l1-mx), e2 = expf(l2-mx), e3 = expf(l3-mx);
        float inv = 1.0f / (e0+e1+e2+e3);
        float p0 = e0*inv, p1 = e1*inv, p2 = e2*inv, p3 = e3*inv;

        float pb[DD];
        #pragma unroll
        for (int d = 0; d < DD; d++) pb[d] = boxes[r*DD + d];

        const int tb0 = b * NTGT;
        for (int t = tid; t < TOT_T; t += 256) {
            float s = 0.0f;
            #pragma unroll
            for (int d = 0; d < DD; d++) s += fabsf(pb[d] - s_tb[t*DD + d]);
            const int lab = s_lab[t];
            const float pc = (lab == 0) ? p0 : (lab == 1) ? p1 : (lab == 2) ? p2 : p3;
            const float c = s - pc;
            if (writeC) C[(size_t)r * TOT_T + t] = c;
            const unsigned int ti = (unsigned int)(t - tb0);
            if (ti < NTGT) g_costT[((size_t)(b*NTGT + ti) << 10) + q] = c;
        }
    }
}

// ---------------------------------------------------------------------------
// Kernel 2: 4-warp JV Hungarian per batch with row-reduction + greedy init.
//   u[i] = row min (dual-feasible), greedy tight-edge matching, then
//   shortest-augmenting-path (Dijkstra) phases ONLY for collided rows.
//   Optimal assignment is unique for continuous random costs -> output
//   identical to the reference e-maxx JV.
//   Phase internals: absolute-distance D, NaN-poison for used columns,
//   deferred u/v fixups (proven in rounds 4-5).
// ---------------------------------------------------------------------------
__device__ __forceinline__ unsigned fkey(float f) {
    unsigned b = __float_as_uint(f);
    return (b & 0x80000000u) ? ~b : (b | 0x80000000u);
}
__device__ __forceinline__ float funkey(unsigned k) {
    return __uint_as_float((k & 0x80000000u) ? (k & 0x7fffffffu) : ~k);
}
__device__ __forceinline__ unsigned redux_min(unsigned x) {
    unsigned r;
    asm volatile("redux.sync.min.u32 %0, %1, 0xffffffff;" : "=r"(r) : "r"(x));
    return r;
}

__global__ __launch_bounds__(TPB, 1)
void hungarian_cta(float* __restrict__ outF, int* __restrict__ outI, int mode)
{
    const int b    = blockIdx.x;
    const int tid  = threadIdx.x;
    const int lane = tid & 31;
    const int w    = tid >> 5;
    const float* __restrict__ cost = g_costT + (size_t)b * NN * MM;

    __shared__ float vneg[MM];          // -v[j] at index j-1 (phase-constant)
    __shared__ float D[MM];             // absolute distance; NaN while used
    __shared__ int   way[MM];           // predecessor column, index j-1
    __shared__ float u[NN + 1];
    __shared__ int   p[MM + 1];         // col -> matched row (0 = free)
    __shared__ int   jmin[NN];          // row argmin column (0-based)
    __shared__ int   pend[NN];          // rows needing a Dijkstra phase
    __shared__ int   s_pendCnt;
    __shared__ int   lj[NN + 8];        // used-column log
    __shared__ float lS[NN + 8];
    __shared__ unsigned pk[NWARP];      // per-warp partial: key
    __shared__ unsigned pjx[NWARP];     // per-warp partial: col index

    for (int x = tid; x < MM; x += TPB) { vneg[x] = 0.0f; p[x + 1] = 0; }
    if (tid == 0) p[0] = 0;

    // ---- row minima: u[i] = min_j cost[i][j], jmin = lowest argmin ----
    for (int r = w; r < NN; r += NWARP) {
        const float4* __restrict__ rowp = (const float4*)(cost + (size_t)r * MM);
        float mv = CUDART_INF_F; int mj = 0;
        #pragma unroll
        for (int k = 0; k < 8; k++) {
            const int q4 = k * 32 + lane;          // ascending j within lane
            const float4 rv = __ldg(rowp + q4);
            const int jb = q4 * 4;
            if (rv.x < mv) { mv = rv.x; mj = jb + 0; }
            if (rv.y < mv) { mv = rv.y; mj = jb + 1; }
            if (rv.z < mv) { mv = rv.z; mj = jb + 2; }
            if (rv.w < mv) { mv = rv.w; mj = jb + 3; }
        }
        const unsigned kv = fkey(mv);
        const unsigned gk = redux_min(kv);
        const unsigned cand = (kv == gk) ? (unsigned)mj : 0xffffffffu;
        const unsigned gj = redux_min(cand);
        if (lane == 0) { u[r + 1] = funkey(gk); jmin[r] = (int)gj; }
    }
    __syncthreads();

    // ---- greedy tight-edge matching (serial, deterministic) ----
    if (tid == 0) {
        int pc = 0;
        for (int ri = 1; ri <= NN; ri++) {
            const int j = jmin[ri - 1] + 1;
            if (p[j] == 0) p[j] = ri;
            else           pend[pc++] = ri;
        }
        s_pendCnt = pc;
    }
    __syncthreads();
    const int pendCnt = s_pendCnt;

    const int q0  = w * 64 + lane;      // this thread's two float4 slots
    const int q1  = q0 + 32;
    const int jb0 = q0 * 4 + 1;         // 1-based j of chunk0 elem 0
    const int jb1 = q1 * 4 + 1;
    const float NANF = __int_as_float(0x7fffffff);

    for (int t0 = 0; t0 < pendCnt; t0++) {
        const int i = pend[t0];

        // ---- phase init ----
        ((float4*)D)[q0] = make_float4(1e9f, 1e9f, 1e9f, 1e9f);
        ((float4*)D)[q1] = make_float4(1e9f, 1e9f, 1e9f, 1e9f);
        const float4 vv0 = ((const float4*)vneg)[q0];
        const float4 vv1 = ((const float4*)vneg)[q1];
        if (tid == 0) { p[0] = i; lj[0] = 0; lS[0] = 0.0f; }
        __syncthreads();

        int   j0 = 0, cnt = 1;
        float S  = 0.0f;
        int   i0 = i;
        const float4* rowp = (const float4*)(cost + (size_t)(i0 - 1) * MM);
        float4 rv0 = __ldg(rowp + q0);
        float4 rv1 = __ldg(rowp + q1);
        float  ui0 = u[i0];

        while (true) {
            const float off = S - ui0;
            float4 D0 = ((const float4*)D)[q0];
            float4 D1 = ((const float4*)D)[q1];

            float bv = CUDART_INF_F; int bj = 0x3fffffff;
            {
                const float x0 = rv0.x + vv0.x + off;
                const float x1 = rv0.y + vv0.y + off;
                const float x2 = rv0.z + vv0.z + off;
                const float x3 = rv0.w + vv0.w + off;
                if (x0 < D0.x) { D0.x = x0; way[jb0 - 1 + 0] = j0; }
                if (x1 < D0.y) { D0.y = x1; way[jb0 - 1 + 1] = j0; }
                if (x2 < D0.z) { D0.z = x2; way[jb0 - 1 + 2] = j0; }
                if (x3 < D0.w) { D0.w = x3; way[jb0 - 1 + 3] = j0; }
                ((float4*)D)[q0] = D0;
                if (D0.x < bv) { bv = D0.x; bj = jb0 + 0; }
                if (D0.y < bv) { bv = D0.y; bj = jb0 + 1; }
                if (D0.z < bv) { bv = D0.z; bj = jb0 + 2; }
                if (D0.w < bv) { bv = D0.w; bj = jb0 + 3; }
            }
            {
                const float x0 = rv1.x + vv1.x + off;
                const float x1 = rv1.y + vv1.y + off;
                const float x2 = rv1.z + vv1.z + off;
                const float x3 = rv1.w + vv1.w + off;
                if (x0 < D1.x) { D1.x = x0; way[jb1 - 1 + 0] = j0; }
                if (x1 < D1.y) { D1.y = x1; way[jb1 - 1 + 1] = j0; }
                if (x2 < D1.z) { D1.z = x2; way[jb1 - 1 + 2] = j0; }
                if (x3 < D1.w) { D1.w = x3; way[jb1 - 1 + 3] = j0; }
                ((float4*)D)[q1] = D1;
                if (D1.x < bv) { bv = D1.x; bj = jb1 + 0; }
                if (D1.y < bv) { bv = D1.y; bj = jb1 + 1; }
                if (D1.z < bv) { bv = D1.z; bj = jb1 + 2; }
                if (D1.w < bv) { bv = D1.w; bj = jb1 + 3; }
            }

            // per-warp argmin (ties -> lowest j)
            const unsigned kv = fkey(bv);
            const unsigned gk = redux_min(kv);
            const unsigned cand = (kv == gk) ? (unsigned)bj : 0xffffffffu;
            const unsigned gj = redux_min(cand);
            if (lane == 0) { pk[w] = gk; pjx[w] = gj; }
            __syncthreads();                               // bar 1

            unsigned bk = pk[0], bi = pjx[0];
            #pragma unroll
            for (int t = 1; t < NWARP; t++) {
                const unsigned k2 = pk[t], i2 = pjx[t];
                if (k2 < bk || (k2 == bk && i2 < bi)) { bk = k2; bi = i2; }
            }
            S  = funkey(bk);
            j0 = (int)bi;

            const int pi1 = p[j0];
            if (pi1 == 0) break;                           // uniform exit

            // prefetch next row BEFORE bar2 -> latency overlaps the barrier
            i0   = pi1;
            rowp = (const float4*)(cost + (size_t)(i0 - 1) * MM);
            rv0  = __ldg(rowp + q0);
            rv1  = __ldg(rowp + q1);
            ui0  = u[i0];
            if (tid == 0) { lj[cnt] = j0; lS[cnt] = S; D[j0 - 1] = NANF; }
            cnt++;
            __syncthreads();                               // bar 2
        }

        // ---- deferred u/v fixups (pre-augmentation p), then augment ----
        int jt = 0, pjt = 0; float amt = 0.0f;
        const bool have = (tid < cnt);
        if (have) { jt = lj[tid]; pjt = p[jt]; amt = S - lS[tid]; }
        __syncthreads();     // all p reads done before tid0 rewrites p
        if (have) {
            u[pjt] += amt;                       // distinct rows per entry
            if (jt) vneg[jt - 1] += amt;         // v[j] -= amt
        }
        if (tid == 0) {
            int j = j0;
            while (j) { const int jn = way[j - 1]; p[j] = p[jn]; j = jn; }
        }
        __syncthreads();     // u/vneg/p stable before next phase init
    }

    // matched_query[target] = query index (0-based)
    for (int x = tid; x < MM; x += TPB) {
        const int pi = p[x + 1];
        if (pi > 0) {
            if (mode == 0) outF[b * NN + pi - 1] = (float)x;
            else           outI[b * NN + pi - 1] = x;
        }
    }
}

// ---------------------------------------------------------------------------
extern "C" void kernel_launch(void* const* d_in, const int* in_sizes, int n_in,
                              void* d_out, int out_size)
{
    const float* logits = (const float*)d_in[0];   // (16,1024,4)
    const float* boxes  = (const float*)d_in[1];   // (16,1024,6)
    const int*   labels = (const int*)  d_in[2];   // (16,96)
    const float* tgt    = (const float*)d_in[3];   // (16,96,6)

    const long long cElems = (long long)BS * NQ * BS * NTGT;  // 25,165,824
    const int matchedElems = BS * NTGT;                        // 1,536

    const int writeC = ((long long)out_size >= cElems) ? 1 : 0;
    build_cost_kernel<<<NQ * BS / 16, 256>>>(logits, boxes, labels, tgt,
                                             (float*)d_out, writeC);

    if ((long long)out_size >= cElems + matchedElems) {
        hungarian_cta<<<BS, TPB>>>((float*)d_out + cElems, nullptr, 0);
    } else if (!writeC && out_size >= matchedElems) {
        hungarian_cta<<<BS, TPB>>>(nullptr, (int*)d_out, 1);
    }
}

// round 17
// speedup vs baseline: 1.4848x; 1.4848x over previous
#include <cuda_runtime.h>
#include <math_constants.h>

#define BS   16
#define NQ   1024
#define NTGT 96
#define NCLS 4
#define DD   6
#define TOT_T (BS*NTGT)   // 1536
#define MM   NQ           // columns (queries) = 1024
#define NN   NTGT         // rows (targets)    = 96
#define NWARP 8
#define TPB  (NWARP*32)   // 256
#define BTPB  384         // build threads: 384*4 = 1536 targets
#define BROWS 16          // rows per build block (1024 % 16 == 0 -> b const/block)

// transposed diagonal cost blocks: costT[b][i][q], i=target, q=query
__device__ float g_costT[BS * NTGT * NQ];   // ~6.3 MB static device scratch

// ---------------------------------------------------------------------------
// Kernel 1: C = L1cdist(pred_boxes, tgt_boxes) - softmax(pred_logits)[tgt_ids]
// Targets register-resident (4/thread), softmax once per row, float4 C stores.
// Also writes the per-batch diagonal block, transposed, into g_costT.
// ---------------------------------------------------------------------------
__global__ __launch_bounds__(BTPB)
void build_cost_kernel(const float* __restrict__ logits,
                       const float* __restrict__ boxes,
                       const int*   __restrict__ labels,
                       const float* __restrict__ tgt,
                       float* __restrict__ C, int writeC)
{
    __shared__ float s_rp[BROWS][12];   // p0..p3, box[0..5]
    const int tid = threadIdx.x;
    const int r0  = blockIdx.x * BROWS;
    const int b   = r0 >> 10;           // constant within block
    const int t0  = tid * 4;            // 4 consecutive targets per thread

    // ---- per-thread target data (registers) ----
    float tb[4][DD];
    {
        const float4* tp = (const float4*)(tgt + (size_t)t0 * DD); // 24 floats
        float4 a0 = __ldg(tp + 0), a1 = __ldg(tp + 1), a2 = __ldg(tp + 2);
        float4 a3 = __ldg(tp + 3), a4 = __ldg(tp + 4), a5 = __ldg(tp + 5);
        tb[0][0]=a0.x; tb[0][1]=a0.y; tb[0][2]=a0.z; tb[0][3]=a0.w; tb[0][4]=a1.x; tb[0][5]=a1.y;
        tb[1][0]=a1.z; tb[1][1]=a1.w; tb[1][2]=a2.x; tb[1][3]=a2.y; tb[1][4]=a2.z; tb[1][5]=a2.w;
        tb[2][0]=a3.x; tb[2][1]=a3.y; tb[2][2]=a3.z; tb[2][3]=a3.w; tb[2][4]=a4.x; tb[2][5]=a4.y;
        tb[3][0]=a4.z; tb[3][1]=a4.w; tb[3][2]=a5.x; tb[3][3]=a5.y; tb[3][4]=a5.z; tb[3][5]=a5.w;
    }
    const int4 lb4 = __ldg((const int4*)(labels + t0));
    const int lab0 = lb4.x, lab1 = lb4.y, lab2 = lb4.z, lab3 = lb4.w;

    // ---- per-row params: softmax + box, once per row ----
    if (tid < BROWS) {
        const int r = r0 + tid;
        const float4 lg = __ldg((const float4*)(logits + (size_t)r * 4));
        float mx = fmaxf(fmaxf(lg.x, lg.y), fmaxf(lg.z, lg.w));
        float e0 = expf(lg.x - mx), e1 = expf(lg.y - mx);
        float e2 = expf(lg.z - mx), e3 = expf(lg.w - mx);
        float inv = 1.0f / (e0 + e1 + e2 + e3);
        s_rp[tid][0] = e0 * inv; s_rp[tid][1] = e1 * inv;
        s_rp[tid][2] = e2 * inv; s_rp[tid][3] = e3 * inv;
        const float* bx = boxes + (size_t)r * DD;
        #pragma unroll
        for (int d = 0; d < DD; d++) s_rp[tid][4 + d] = __ldg(bx + d);
    }
    __syncthreads();

    const int dlo = b * NTGT;               // diagonal target range [dlo, dlo+96)
    #pragma unroll 1
    for (int rr = 0; rr < BROWS; rr++) {
        const int r = r0 + rr;
        const int q = r & 1023;
        const float p0 = s_rp[rr][0], p1 = s_rp[rr][1];
        const float p2 = s_rp[rr][2], p3 = s_rp[rr][3];
        float pb[DD];
        #pragma unroll
        for (int d = 0; d < DD; d++) pb[d] = s_rp[rr][4 + d];

        float c[4];
        #pragma unroll
        for (int k = 0; k < 4; k++) {
            float s = 0.0f;
            #pragma unroll
            for (int d = 0; d < DD; d++) s += fabsf(pb[d] - tb[k][d]);
            const int lab = (k == 0) ? lab0 : (k == 1) ? lab1 : (k == 2) ? lab2 : lab3;
            const float pc = (lab == 0) ? p0 : (lab == 1) ? p1 : (lab == 2) ? p2 : p3;
            c[k] = s - pc;
        }
        if (writeC)
            ((float4*)(C + (size_t)r * TOT_T))[tid] = make_float4(c[0], c[1], c[2], c[3]);
        #pragma unroll
        for (int k = 0; k < 4; k++) {
            const unsigned ti = (unsigned)(t0 + k - dlo);
            if (ti < NTGT) g_costT[((size_t)(b * NTGT + ti) << 10) + q] = c[k];
        }
    }
}

// ---------------------------------------------------------------------------
// Kernel 2: 8-warp JV Hungarian per batch with row-reduction + greedy init.
//   (proven structure from rounds 4-16; now 1 float4 slot per thread)
// ---------------------------------------------------------------------------
__device__ __forceinline__ unsigned fkey(float f) {
    unsigned b = __float_as_uint(f);
    return (b & 0x80000000u) ? ~b : (b | 0x80000000u);
}
__device__ __forceinline__ float funkey(unsigned k) {
    return __uint_as_float((k & 0x80000000u) ? (k & 0x7fffffffu) : ~k);
}
__device__ __forceinline__ unsigned redux_min(unsigned x) {
    unsigned r;
    asm volatile("redux.sync.min.u32 %0, %1, 0xffffffff;" : "=r"(r) : "r"(x));
    return r;
}

__global__ __launch_bounds__(TPB, 1)
void hungarian_cta(float* __restrict__ outF, int* __restrict__ outI, int mode)
{
    const int b    = blockIdx.x;
    const int tid  = threadIdx.x;
    const int lane = tid & 31;
    const int w    = tid >> 5;
    const float* __restrict__ cost = g_costT + (size_t)b * NN * MM;

    __shared__ float vneg[MM];          // -v[j] at index j-1 (phase-constant)
    __shared__ float D[MM];             // absolute distance; NaN while used
    __shared__ int   way[MM];           // predecessor column, index j-1
    __shared__ float u[NN + 1];
    __shared__ int   p[MM + 1];         // col -> matched row (0 = free)
    __shared__ int   jmin[NN];          // row argmin column (0-based)
    __shared__ int   pend[NN];          // rows needing a Dijkstra phase
    __shared__ int   s_pendCnt;
    __shared__ int   lj[NN + 8];        // used-column log
    __shared__ float lS[NN + 8];
    __shared__ unsigned pk[NWARP];      // per-warp partial: key
    __shared__ unsigned pjx[NWARP];     // per-warp partial: col index

    for (int x = tid; x < MM; x += TPB) { vneg[x] = 0.0f; p[x + 1] = 0; }
    if (tid == 0) p[0] = 0;

    // ---- row minima: u[i] = min_j cost[i][j], jmin = lowest argmin ----
    for (int r = w; r < NN; r += NWARP) {
        const float4* __restrict__ rowp = (const float4*)(cost + (size_t)r * MM);
        float mv = CUDART_INF_F; int mj = 0;
        #pragma unroll
        for (int k = 0; k < 8; k++) {
            const int q4 = k * 32 + lane;          // ascending j within lane
            const float4 rv = __ldg(rowp + q4);
            const int jb = q4 * 4;
            if (rv.x < mv) { mv = rv.x; mj = jb + 0; }
            if (rv.y < mv) { mv = rv.y; mj = jb + 1; }
            if (rv.z < mv) { mv = rv.z; mj = jb + 2; }
            if (rv.w < mv) { mv = rv.w; mj = jb + 3; }
        }
        const unsigned kv = fkey(mv);
        const unsigned gk = redux_min(kv);
        const unsigned cand = (kv == gk) ? (unsigned)mj : 0xffffffffu;
        const unsigned gj = redux_min(cand);
        if (lane == 0) { u[r + 1] = funkey(gk); jmin[r] = (int)gj; }
    }
    __syncthreads();

    // ---- greedy tight-edge matching (serial, deterministic) ----
    if (tid == 0) {
        int pc = 0;
        for (int ri = 1; ri <= NN; ri++) {
            const int j = jmin[ri - 1] + 1;
            if (p[j] == 0) p[j] = ri;
            else           pend[pc++] = ri;
        }
        s_pendCnt = pc;
    }
    __syncthreads();
    const int pendCnt = s_pendCnt;

    const int q0  = tid;                // this thread's single float4 slot
    const int jb0 = q0 * 4 + 1;         // 1-based j of elem 0
    const float NANF = __int_as_float(0x7fffffff);

    for (int t0 = 0; t0 < pendCnt; t0++) {
        const int i = pend[t0];

        // ---- phase init ----
        ((float4*)D)[q0] = make_float4(1e9f, 1e9f, 1e9f, 1e9f);
        const float4 vv0 = ((const float4*)vneg)[q0];
        if (tid == 0) { p[0] = i; lj[0] = 0; lS[0] = 0.0f; }
        __syncthreads();

        int   j0 = 0, cnt = 1;
        float S  = 0.0f;
        int   i0 = i;
        const float4* rowp = (const float4*)(cost + (size_t)(i0 - 1) * MM);
        float4 rv0 = __ldg(rowp + q0);
        float  ui0 = u[i0];

        while (true) {
            const float off = S - ui0;
            float4 D0 = ((const float4*)D)[q0];

            float bv = CUDART_INF_F; int bj = 0x3fffffff;
            const float x0 = rv0.x + vv0.x + off;
            const float x1 = rv0.y + vv0.y + off;
            const float x2 = rv0.z + vv0.z + off;
            const float x3 = rv0.w + vv0.w + off;
            if (x0 < D0.x) { D0.x = x0; way[jb0 - 1 + 0] = j0; }
            if (x1 < D0.y) { D0.y = x1; way[jb0 - 1 + 1] = j0; }
            if (x2 < D0.z) { D0.z = x2; way[jb0 - 1 + 2] = j0; }
            if (x3 < D0.w) { D0.w = x3; way[jb0 - 1 + 3] = j0; }
            ((float4*)D)[q0] = D0;
            if (D0.x < bv) { bv = D0.x; bj = jb0 + 0; }
            if (D0.y < bv) { bv = D0.y; bj = jb0 + 1; }
            if (D0.z < bv) { bv = D0.z; bj = jb0 + 2; }
            if (D0.w < bv) { bv = D0.w; bj = jb0 + 3; }

            // per-warp argmin (ties -> lowest j)
            const unsigned kv = fkey(bv);
            const unsigned gk = redux_min(kv);
            const unsigned cand = (kv == gk) ? (unsigned)bj : 0xffffffffu;
            const unsigned gj = redux_min(cand);
            if (lane == 0) { pk[w] = gk; pjx[w] = gj; }
            __syncthreads();                               // bar 1

            unsigned bk = pk[0], bi = pjx[0];
            #pragma unroll
            for (int t = 1; t < NWARP; t++) {
                const unsigned k2 = pk[t], i2 = pjx[t];
                if (k2 < bk || (k2 == bk && i2 < bi)) { bk = k2; bi = i2; }
            }
            S  = funkey(bk);
            j0 = (int)bi;

            const int pi1 = p[j0];
            if (pi1 == 0) break;                           // uniform exit

            // prefetch next row BEFORE bar2 -> latency overlaps the barrier
            i0   = pi1;
            rowp = (const float4*)(cost + (size_t)(i0 - 1) * MM);
            rv0  = __ldg(rowp + q0);
            ui0  = u[i0];
            if (tid == 0) { lj[cnt] = j0; lS[cnt] = S; D[j0 - 1] = NANF; }
            cnt++;
            __syncthreads();                               // bar 2
        }

        // ---- deferred u/v fixups (pre-augmentation p), then augment ----
        int jt = 0, pjt = 0; float amt = 0.0f;
        const bool have = (tid < cnt);
        if (have) { jt = lj[tid]; pjt = p[jt]; amt = S - lS[tid]; }
        __syncthreads();     // all p reads done before tid0 rewrites p
        if (have) {
            u[pjt] += amt;                       // distinct rows per entry
            if (jt) vneg[jt - 1] += amt;         // v[j] -= amt
        }
        if (tid == 0) {
            int j = j0;
            while (j) { const int jn = way[j - 1]; p[j] = p[jn]; j = jn; }
        }
        __syncthreads();     // u/vneg/p stable before next phase init
    }

    // matched_query[target] = query index (0-based)
    for (int x = tid; x < MM; x += TPB) {
        const int pi = p[x + 1];
        if (pi > 0) {
            if (mode == 0) outF[b * NN + pi - 1] = (float)x;
            else           outI[b * NN + pi - 1] = x;
        }
    }
}

// ---------------------------------------------------------------------------
extern "C" void kernel_launch(void* const* d_in, const int* in_sizes, int n_in,
                              void* d_out, int out_size)
{
    const float* logits = (const float*)d_in[0];   // (16,1024,4)
    const float* boxes  = (const float*)d_in[1];   // (16,1024,6)
    const int*   labels = (const int*)  d_in[2];   // (16,96)
    const float* tgt    = (const float*)d_in[3];   // (16,96,6)

    const long long cElems = (long long)BS * NQ * BS * NTGT;  // 25,165,824
    const int matchedElems = BS * NTGT;                        // 1,536

    const int writeC = ((long long)out_size >= cElems) ? 1 : 0;
    build_cost_kernel<<<(BS * NQ) / BROWS, BTPB>>>(logits, boxes, labels, tgt,
                                                   (float*)d_out, writeC);

    if ((long long)out_size >= cElems + matchedElems) {
        hungarian_cta<<<BS, TPB>>>((float*)d_out + cElems, nullptr, 0);
    } else if (!writeC && out_size >= matchedElems) {
        hungarian_cta<<<BS, TPB>>>(nullptr, (int*)d_out, 1);
    }
}